// round 16
// baseline (speedup 1.0000x reference)
#include <cuda_runtime.h>
#include <cuda_fp16.h>
#include <math.h>
#include <stdint.h>

#define SN 3072
#define DIN 512
#define NH 16
#define HD_ 64
#define HDIM 1024   // NH * HD_

#define FULLM 0xffffffffu
#define LOG2E 1.4426950408889634f
#define QSC   0.18033688011112042f   // 0.125 * log2(e)

// -------- scratch (device globals; no allocations allowed) --------
__device__ __half g_qh[NH * SN * HD_];   // [H][N][D] fp16, pre-scaled 0.125*log2e
__device__ __half g_kh[NH * SN * HD_];
__device__ __half g_vh[NH * SN * HD_];
__device__ __half g_vals[SN * HDIM];
__device__ __half g_hid[SN * HDIM];
__device__ float  g_bm[SN * SN];         // mask? bias*log2e-5 : -9e15, PERMUTED per 64-col block
// fp16 copies of inputs/weights
__device__ __half g_qr[SN * DIN];
__device__ __half g_kr[SN * DIN];
__device__ __half g_vr[SN * DIN];
__device__ __half g_Wq[HDIM * DIN];
__device__ __half g_Wk[HDIM * DIN];
__device__ __half g_Wv[HDIM * DIN];
__device__ __half g_Wo1[HDIM * HDIM];
__device__ __half g_Wo2[DIN * HDIM];

// ---------------- helpers ----------------
__device__ __forceinline__ void mma16(float* c, const uint32_t* a, uint32_t b0, uint32_t b1) {
    asm volatile(
        "mma.sync.aligned.m16n8k16.row.col.f32.f16.f16.f32 "
        "{%0,%1,%2,%3},{%4,%5,%6,%7},{%8,%9},{%0,%1,%2,%3};"
        : "+f"(c[0]), "+f"(c[1]), "+f"(c[2]), "+f"(c[3])
        : "r"(a[0]), "r"(a[1]), "r"(a[2]), "r"(a[3]), "r"(b0), "r"(b1));
}

__device__ __forceinline__ void ldmx4(uint32_t& d0, uint32_t& d1, uint32_t& d2, uint32_t& d3,
                                      uint32_t saddr) {
    asm volatile("ldmatrix.sync.aligned.m8n8.x4.shared.b16 {%0,%1,%2,%3}, [%4];"
                 : "=r"(d0), "=r"(d1), "=r"(d2), "=r"(d3) : "r"(saddr));
}
__device__ __forceinline__ void ldmx4t(uint32_t& d0, uint32_t& d1, uint32_t& d2, uint32_t& d3,
                                       uint32_t saddr) {
    asm volatile("ldmatrix.sync.aligned.m8n8.x4.trans.shared.b16 {%0,%1,%2,%3}, [%4];"
                 : "=r"(d0), "=r"(d1), "=r"(d2), "=r"(d3) : "r"(saddr));
}

__device__ __forceinline__ void cpa16(void* sdst, const void* gsrc) {
    uint32_t sa = (uint32_t)__cvta_generic_to_shared(sdst);
    asm volatile("cp.async.cg.shared.global [%0], [%1], 16;" :: "r"(sa), "l"(gsrc));
}
__device__ __forceinline__ void cpa_commit() { asm volatile("cp.async.commit_group;"); }
__device__ __forceinline__ void cpa_wait1()  { asm volatile("cp.async.wait_group 1;"); }

__device__ __forceinline__ uint32_t packh2(float a, float b) {
    __half2 h = __floats2half2_rn(a, b);
    return *reinterpret_cast<uint32_t*>(&h);
}
__device__ __forceinline__ uint32_t h2ex2(uint32_t x) {
    uint32_t r;
    asm("ex2.approx.f16x2 %0, %1;" : "=r"(r) : "r"(x));
    return r;
}
__device__ __forceinline__ float ex2f(float x) {
    float r;
    asm("ex2.approx.f32 %0, %1;" : "=f"(r) : "f"(x));
    return r;
}
// mish(x) = x * tanh(softplus(x)) = x * t(t+2)/(t(t+2)+2), t = e^x
__device__ __forceinline__ float mish_f(float x) {
    float t = ex2f(x * LOG2E);
    float num = t * (t + 2.0f);
    float m = x * __fdividef(num, num + 2.0f);
    return (x > 40.f) ? x : m;
}

// ============================================================
// merged prepass: z 0-7 fp16-convert, z 8-13 bm fuse (permuted) + passthrough
// grid (1536, 1, 14), 256 threads
// ============================================================
__global__ void prepass_kernel(
    const float* q, const float* k, const float* v,
    const float* Wq, const float* Wk, const float* Wv,
    const float* Wo1, const float* Wo2,
    const float* bias, const int* mask, float* outbias)
{
    if (blockIdx.z < 8) {
        const float* src; __half* dst; int n4;
        switch (blockIdx.z) {
            case 0: src = q;   dst = g_qr;  n4 = SN * DIN / 4;    break;
            case 1: src = k;   dst = g_kr;  n4 = SN * DIN / 4;    break;
            case 2: src = v;   dst = g_vr;  n4 = SN * DIN / 4;    break;
            case 3: src = Wq;  dst = g_Wq;  n4 = HDIM * DIN / 4;  break;
            case 4: src = Wk;  dst = g_Wk;  n4 = HDIM * DIN / 4;  break;
            case 5: src = Wv;  dst = g_Wv;  n4 = HDIM * DIN / 4;  break;
            case 6: src = Wo1; dst = g_Wo1; n4 = HDIM * HDIM / 4; break;
            default: src = Wo2; dst = g_Wo2; n4 = DIN * HDIM / 4; break;
        }
        int i4 = blockIdx.x * 256 + threadIdx.x;
        if (i4 >= n4) return;
        float4 x = *(const float4*)(src + (size_t)i4 * 4);
        uint2 r = make_uint2(packh2(x.x, x.y), packh2(x.z, x.w));
        *(uint2*)(dst + (size_t)i4 * 4) = r;
    } else {
        // bm planes: 6 planes x 1536 blocks x 256 threads x 4 elems = SN*SN
        int p = blockIdx.z - 8;
        size_t i = ((size_t)(p * 1536 + blockIdx.x) * 256 + threadIdx.x) * 4;
        float4 b = *(const float4*)(bias + i);
        int4   m = *(const int4*)(mask + i);
        *(float4*)(outbias + i) = b;
        float r[4];
        r[0] = m.x ? fmaf(b.x, LOG2E, -5.f) : -9e15f;
        r[1] = m.y ? fmaf(b.y, LOG2E, -5.f) : -9e15f;
        r[2] = m.z ? fmaf(b.z, LOG2E, -5.f) : -9e15f;
        r[3] = m.w ? fmaf(b.w, LOG2E, -5.f) : -9e15f;
        // permuted store: within 64-col block, c -> ((c&7)>>1)*16 + (c>>3)*2 + (c&1)
        size_t rowbase = (i / 64) * 64;
        int c0 = (int)(i & 63);
        #pragma unroll
        for (int j = 0; j < 4; j += 2) {
            int c = c0 + j;
            int cp = (((c & 7) >> 1) << 4) + ((c >> 3) << 1) + (c & 1);
            *(float2*)(g_bm + rowbase + cp) = make_float2(r[j], r[j + 1]);
        }
    }
}

// ============================================================
// fp16 GEMM body: BM=128, BN=64, BK=64, 256 thr, 3-stage, one barrier.
// MODE 0: scatter [H][N][64] fp16; 1: mish [N][HDIM] fp16; 2: plain fp32
// ============================================================
#define GP 72
#define GEMM_SMEM (3 * (128 * GP + 64 * GP) * 2)

template<int K, int MODE>
__device__ __forceinline__ void gemm_body(
    const __half* __restrict__ A, const __half* __restrict__ W,
    const float* __restrict__ bvec, void* __restrict__ outv, int NC, float scale,
    __half* smg)
{
    __half* AsB = smg;                 // 3 * 128*GP
    __half* WsB = smg + 3 * 128 * GP;  // 3 * 64*GP

    const int tid = threadIdx.x, lane = tid & 31, w = tid >> 5;
    const int gq = lane >> 2, tig = lane & 3;
    const int wrow = w * 16;
    const int row0 = blockIdx.y * 128, col0 = blockIdx.x * 64;
    const int NIT = K / 64;

    const uint32_t sA0 = (uint32_t)__cvta_generic_to_shared(AsB);
    const uint32_t sW0 = (uint32_t)__cvta_generic_to_shared(WsB);
    const uint32_t aLane = (((lane & 7) + ((lane >> 3) & 1) * 8) * GP + ((lane >> 4) & 1) * 8) * 2;
    const uint32_t wLane = (((lane & 7) + ((lane >> 4) & 1) * 8) * GP + ((lane >> 3) & 1) * 8) * 2;

    auto LOAD = [&](int buf, int it) {
        const int k0 = it * 64;
        __half* Ab = AsB + buf * 128 * GP;
        __half* Wb = WsB + buf * 64 * GP;
        #pragma unroll
        for (int i = 0; i < 4; i++) {
            int id = tid + i * 256, r = id >> 3, sg = (id & 7) * 8;
            cpa16(Ab + r * GP + sg, A + (size_t)(row0 + r) * K + k0 + sg);
        }
        #pragma unroll
        for (int i = 0; i < 2; i++) {
            int id = tid + i * 256, r = id >> 3, sg = (id & 7) * 8;
            cpa16(Wb + r * GP + sg, W + (size_t)(col0 + r) * K + k0 + sg);
        }
    };

    float cf[8][4] = {};
    LOAD(0, 0); cpa_commit();
    if (NIT > 1) LOAD(1, 1);
    cpa_commit();

    for (int it = 0; it < NIT; it++) {
        cpa_wait1();
        __syncthreads();
        if (it + 2 < NIT) LOAD((it + 2) % 3, it + 2);
        cpa_commit();

        const uint32_t sA = sA0 + (it % 3) * (128 * GP * 2) + aLane + wrow * GP * 2;
        const uint32_t sW = sW0 + (it % 3) * (64 * GP * 2) + wLane;
        #pragma unroll
        for (int kk = 0; kk < 4; kk++) {
            uint32_t af[4];
            ldmx4(af[0], af[1], af[2], af[3], sA + kk * 32);
            #pragma unroll
            for (int np = 0; np < 4; np++) {
                uint32_t w0, w1, w2, w3;
                ldmx4(w0, w1, w2, w3, sW + (np * 16 * GP) * 2 + kk * 32);
                mma16(cf[2 * np],     af, w0, w1);
                mma16(cf[2 * np + 1], af, w2, w3);
            }
        }
    }

    const int mr0 = row0 + wrow + gq, mr1 = mr0 + 8;
    #pragma unroll
    for (int n = 0; n < 8; n++) {
        int cg = col0 + n * 8 + tig * 2;
        float b0v = bvec[cg], b1v = bvec[cg + 1];
        float v00 = (cf[n][0] + b0v) * scale, v01 = (cf[n][1] + b1v) * scale;
        float v10 = (cf[n][2] + b0v) * scale, v11 = (cf[n][3] + b1v) * scale;
        if (MODE == 0) {
            __half* out = (__half*)outv;
            int h = cg >> 6, d = cg & 63;
            *(uint32_t*)(out + ((size_t)h * SN + mr0) * HD_ + d) = packh2(v00, v01);
            *(uint32_t*)(out + ((size_t)h * SN + mr1) * HD_ + d) = packh2(v10, v11);
        } else if (MODE == 1) {
            __half* out = (__half*)outv;
            *(uint32_t*)(out + (size_t)mr0 * HDIM + cg) = packh2(mish_f(v00), mish_f(v01));
            *(uint32_t*)(out + (size_t)mr1 * HDIM + cg) = packh2(mish_f(v10), mish_f(v11));
        } else {
            float* out = (float*)outv;
            *(float2*)(out + (size_t)mr0 * NC + cg) = make_float2(v00, v01);
            *(float2*)(out + (size_t)mr1 * NC + cg) = make_float2(v10, v11);
        }
    }
}

template<int K, int MODE>
__global__ void __launch_bounds__(256, 2) gemm_f16(
    const __half* __restrict__ A, const __half* __restrict__ W,
    const float* __restrict__ bvec, void* __restrict__ outv, int NC, float scale)
{
    extern __shared__ __half smg[];
    gemm_body<K, MODE>(A, W, bvec, outv, NC, scale, smg);
}

__global__ void __launch_bounds__(256, 2) gemm_proj3(
    const float* __restrict__ bq, const float* __restrict__ bk,
    const float* __restrict__ bv)
{
    extern __shared__ __half smg[];
    if (blockIdx.z == 0)
        gemm_body<DIN, 0>(g_qr, g_Wq, bq, g_qh, HDIM, QSC, smg);
    else if (blockIdx.z == 1)
        gemm_body<DIN, 0>(g_kr, g_Wk, bk, g_kh, HDIM, 1.0f, smg);
    else
        gemm_body<DIN, 0>(g_vr, g_Wv, bv, g_vh, HDIM, 1.0f, smg);
}

// ============================================================
// Flash attention (R12/R13 structure): CTA = (head, 128 Q rows), 256 thr,
// 8 warps x 16 rows, triple-buffered K/V, ONE barrier per key block.
// bm is pre-permuted -> 4x float4 per row per block.
// ============================================================
#define AP 72
#define KVB (64 * AP)
#define ATTN_SMEM (3 * 2 * KVB * 2)
#define NBLK (SN / 64)

__global__ void __launch_bounds__(256, 2) attn_mma(const float* __restrict__ bm)
{
    extern __shared__ __half sma[];
    __half* KsB = sma;                  // 3 * [64][AP]
    __half* VsB = sma + 3 * KVB;        // 3 * [64][AP]

    const int h = blockIdx.x, q0 = blockIdx.y * 128;
    const int tid = threadIdx.x, lane = tid & 31, w = tid >> 5;
    const int gq = lane >> 2, tig = lane & 3;
    const int wrow = w * 16;
    const int r0 = wrow + gq, r1 = r0 + 8;

    const __half* qp    = g_qh + ((size_t)h * SN + q0) * HD_;
    const __half* kbase = g_kh + (size_t)h * SN * HD_;
    const __half* vbase = g_vh + (size_t)h * SN * HD_;

    const uint32_t sK0 = (uint32_t)__cvta_generic_to_shared(KsB);
    const uint32_t sV0 = (uint32_t)__cvta_generic_to_shared(VsB);
    const uint32_t kLane = (((lane & 7) + ((lane >> 4) & 1) * 8) * AP + ((lane >> 3) & 1) * 8) * 2;
    const uint32_t vLane = (((lane & 7) + ((lane >> 3) & 1) * 8) * AP + ((lane >> 4) & 1) * 8) * 2;

    auto LOADKV = [&](int buf, int jb) {
        const int k0 = jb * 64;
        __half* Ks = KsB + buf * KVB;
        __half* Vs = VsB + buf * KVB;
        #pragma unroll
        for (int i = 0; i < 2; i++) {
            int id = tid + i * 256, r = id >> 3, sg = (id & 7) * 8;
            cpa16(Ks + r * AP + sg, kbase + (size_t)(k0 + r) * HD_ + sg);
        }
        #pragma unroll
        for (int i = 0; i < 2; i++) {
            int id = tid + i * 256, r = id >> 3, sg = (id & 7) * 8;
            cpa16(Vs + r * AP + sg, vbase + (size_t)(k0 + r) * HD_ + sg);
        }
    };

    // Q fragments (fp16 pairs), pre-scaled 0.125*log2e
    uint32_t qf[4][4];
    #pragma unroll
    for (int kk = 0; kk < 4; kk++) {
        qf[kk][0] = *(const uint32_t*)(qp + r0 * HD_ + kk * 16 + 2 * tig);
        qf[kk][1] = *(const uint32_t*)(qp + r1 * HD_ + kk * 16 + 2 * tig);
        qf[kk][2] = *(const uint32_t*)(qp + r0 * HD_ + kk * 16 + 2 * tig + 8);
        qf[kk][3] = *(const uint32_t*)(qp + r1 * HD_ + kk * 16 + 2 * tig + 8);
    }

    LOADKV(0, 0); cpa_commit();
    LOADKV(1, 1); cpa_commit();

    float of[8][4] = {};
    float l0 = 0.f, l1 = 0.f;

    const size_t brow0 = (size_t)(q0 + r0) * SN + tig * 16;
    const size_t brow1 = (size_t)(q0 + r1) * SN + tig * 16;

    for (int jb = 0; jb < NBLK; jb++) {
        const int k0 = jb * 64;

        // bm loads: permuted layout -> 4 float4 per row
        float b0v[16], b1v[16];
        {
            const float4* p0 = (const float4*)(bm + brow0 + k0);
            const float4* p1 = (const float4*)(bm + brow1 + k0);
            #pragma unroll
            for (int i = 0; i < 4; i++) {
                *(float4*)(b0v + 4 * i) = p0[i];
                *(float4*)(b1v + 4 * i) = p1[i];
            }
        }
        float sf[8][4];
        #pragma unroll
        for (int n = 0; n < 8; n++) {
            sf[n][0] = b0v[2 * n]; sf[n][1] = b0v[2 * n + 1];
            sf[n][2] = b1v[2 * n]; sf[n][3] = b1v[2 * n + 1];
        }

        cpa_wait1();
        __syncthreads();
        if (jb + 2 < NBLK) LOADKV((jb + 2) % 3, jb + 2);
        cpa_commit();

        const uint32_t sK = sK0 + (jb % 3) * (KVB * 2) + kLane;
        const uint32_t sV = sV0 + (jb % 3) * (KVB * 2) + vLane;

        // S = log2-domain logits
        #pragma unroll
        for (int kk = 0; kk < 4; kk++) {
            #pragma unroll
            for (int np = 0; np < 4; np++) {
                uint32_t b0, b1, b2, b3;
                ldmx4(b0, b1, b2, b3, sK + (np * 16 * AP) * 2 + kk * 32);
                mma16(sf[2 * np],     qf[kk], b0, b1);
                mma16(sf[2 * np + 1], qf[kk], b2, b3);
            }
        }

        // p = 2^S, accumulate row sums, pack fp16 A-frags in place
        uint32_t* sfu = reinterpret_cast<uint32_t*>(&sf[0][0]);
        #pragma unroll
        for (int kk = 0; kk < 4; kk++) {
            uint32_t t0[2], t1[2];
            #pragma unroll
            for (int hh = 0; hh < 2; hh++) {
                int j = 2 * kk + hh;
                uint32_t p01 = h2ex2(packh2(sf[j][0], sf[j][1]));
                uint32_t p23 = h2ex2(packh2(sf[j][2], sf[j][3]));
                __half2 h01 = *reinterpret_cast<__half2*>(&p01);
                __half2 h23 = *reinterpret_cast<__half2*>(&p23);
                l0 += __half2float(h01.x) + __half2float(h01.y);
                l1 += __half2float(h23.x) + __half2float(h23.y);
                t0[hh] = p01;
                t1[hh] = p23;
            }
            sfu[4 * kk + 0] = t0[0];
            sfu[4 * kk + 1] = t1[0];
            sfu[4 * kk + 2] = t0[1];
            sfu[4 * kk + 3] = t1[1];
        }

        // O += P V  (V via ldmatrix.trans)
        #pragma unroll
        for (int kk = 0; kk < 4; kk++) {
            #pragma unroll
            for (int nt = 0; nt < 4; nt++) {
                uint32_t v0, v1, v2, v3;
                ldmx4t(v0, v1, v2, v3, sV + (kk * 16 * AP) * 2 + nt * 32);
                mma16(of[2 * nt],     sfu + 4 * kk, v0, v1);
                mma16(of[2 * nt + 1], sfu + 4 * kk, v2, v3);
            }
        }
    }

    l0 += __shfl_xor_sync(FULLM, l0, 1); l0 += __shfl_xor_sync(FULLM, l0, 2);
    l1 += __shfl_xor_sync(FULLM, l1, 1); l1 += __shfl_xor_sync(FULLM, l1, 2);

    const float inv0 = 1.f / l0, inv1 = 1.f / l1;
    #pragma unroll
    for (int n = 0; n < 8; n++) {
        int c = h * HD_ + n * 8 + tig * 2;
        *(uint32_t*)(g_vals + (size_t)(q0 + r0) * HDIM + c) = packh2(of[n][0] * inv0, of[n][1] * inv0);
        *(uint32_t*)(g_vals + (size_t)(q0 + r1) * HDIM + c) = packh2(of[n][2] * inv1, of[n][3] * inv1);
    }
}

// ============================================================
extern "C" void kernel_launch(void* const* d_in, const int* in_sizes, int n_in,
                              void* d_out, int out_size) {
    const float* q    = (const float*)d_in[0];
    const float* k    = (const float*)d_in[1];
    const float* v    = (const float*)d_in[2];
    const float* bias = (const float*)d_in[3];
    const int*   mask = (const int*)d_in[4];
    const float* Wq   = (const float*)d_in[5];
    const float* bq   = (const float*)d_in[6];
    const float* Wk   = (const float*)d_in[7];
    const float* bk   = (const float*)d_in[8];
    const float* Wv   = (const float*)d_in[9];
    const float* bv   = (const float*)d_in[10];
    const float* Wo1  = (const float*)d_in[11];
    const float* bo1  = (const float*)d_in[12];
    const float* Wo2  = (const float*)d_in[13];
    const float* bo2  = (const float*)d_in[14];
    float* out = (float*)d_out;

    __half *p_vals, *p_hid, *p_Wo1, *p_Wo2;
    float *p_bm;
    cudaGetSymbolAddress((void**)&p_vals, g_vals);
    cudaGetSymbolAddress((void**)&p_hid, g_hid);
    cudaGetSymbolAddress((void**)&p_bm,  g_bm);
    cudaGetSymbolAddress((void**)&p_Wo1, g_Wo1);
    cudaGetSymbolAddress((void**)&p_Wo2, g_Wo2);

    cudaFuncSetAttribute(gemm_proj3,        cudaFuncAttributeMaxDynamicSharedMemorySize, GEMM_SMEM);
    cudaFuncSetAttribute(gemm_f16<HDIM, 1>, cudaFuncAttributeMaxDynamicSharedMemorySize, GEMM_SMEM);
    cudaFuncSetAttribute(gemm_f16<HDIM, 2>, cudaFuncAttributeMaxDynamicSharedMemorySize, GEMM_SMEM);
    cudaFuncSetAttribute(attn_mma, cudaFuncAttributeMaxDynamicSharedMemorySize, ATTN_SMEM);

    dim3 blk(256);

    // 0) merged prepass: converts + bm fuse (permuted) + bias passthrough
    prepass_kernel<<<dim3(1536, 1, 14), blk>>>(q, k, v, Wq, Wk, Wv, Wo1, Wo2,
                                               bias, mask, out + (size_t)SN * DIN);

    // 1) projections (Q pre-scaled by 0.125*log2e)
    dim3 gp(HDIM / 64, SN / 128, 3);
    gemm_proj3<<<gp, blk, GEMM_SMEM>>>(bq, bk, bv);

    // 2) flash attention
    dim3 ga(NH, SN / 128);
    attn_mma<<<ga, blk, ATTN_SMEM>>>(p_bm);

    // 3) MLP
    dim3 g1(HDIM / 64, SN / 128);
    gemm_f16<HDIM, 1><<<g1, blk, GEMM_SMEM>>>(p_vals, p_Wo1, bo1, p_hid, HDIM, 1.0f);
    dim3 g2(DIN / 64, SN / 128);
    gemm_f16<HDIM, 2><<<g2, blk, GEMM_SMEM>>>(p_hid, p_Wo2, bo2, out, DIN, 1.0f);
}

// round 17
// speedup vs baseline: 1.4645x; 1.4645x over previous
#include <cuda_runtime.h>
#include <cuda_fp16.h>
#include <math.h>
#include <stdint.h>

#define SN 3072
#define DIN 512
#define NH 16
#define HD_ 64
#define HDIM 1024   // NH * HD_

#define FULLM 0xffffffffu
#define LOG2E 1.4426950408889634f
#define QSC   0.18033688011112042f   // 0.125 * log2(e)

// -------- scratch (device globals; no allocations allowed) --------
__device__ __half g_qh[NH * SN * HD_];   // [H][N][D] fp16, pre-scaled 0.125*log2e
__device__ __half g_kh[NH * SN * HD_];
__device__ __half g_vh[NH * SN * HD_];
__device__ __half g_vals[SN * HDIM];
__device__ __half g_hid[SN * HDIM];
__device__ float  g_bm[SN * SN];         // mask? bias*log2e-5 : -9e15, PERMUTED per 64-col block
// fp16 copies of inputs/weights
__device__ __half g_qr[SN * DIN];
__device__ __half g_kr[SN * DIN];
__device__ __half g_vr[SN * DIN];
__device__ __half g_Wq[HDIM * DIN];
__device__ __half g_Wk[HDIM * DIN];
__device__ __half g_Wv[HDIM * DIN];
__device__ __half g_Wo1[HDIM * HDIM];
__device__ __half g_Wo2[DIN * HDIM];

// ---------------- helpers ----------------
__device__ __forceinline__ void mma16(float* c, const uint32_t* a, uint32_t b0, uint32_t b1) {
    asm volatile(
        "mma.sync.aligned.m16n8k16.row.col.f32.f16.f16.f32 "
        "{%0,%1,%2,%3},{%4,%5,%6,%7},{%8,%9},{%0,%1,%2,%3};"
        : "+f"(c[0]), "+f"(c[1]), "+f"(c[2]), "+f"(c[3])
        : "r"(a[0]), "r"(a[1]), "r"(a[2]), "r"(a[3]), "r"(b0), "r"(b1));
}

__device__ __forceinline__ void ldmx4(uint32_t& d0, uint32_t& d1, uint32_t& d2, uint32_t& d3,
                                      uint32_t saddr) {
    asm volatile("ldmatrix.sync.aligned.m8n8.x4.shared.b16 {%0,%1,%2,%3}, [%4];"
                 : "=r"(d0), "=r"(d1), "=r"(d2), "=r"(d3) : "r"(saddr));
}
__device__ __forceinline__ void ldmx4t(uint32_t& d0, uint32_t& d1, uint32_t& d2, uint32_t& d3,
                                       uint32_t saddr) {
    asm volatile("ldmatrix.sync.aligned.m8n8.x4.trans.shared.b16 {%0,%1,%2,%3}, [%4];"
                 : "=r"(d0), "=r"(d1), "=r"(d2), "=r"(d3) : "r"(saddr));
}

__device__ __forceinline__ void cpa16(void* sdst, const void* gsrc) {
    uint32_t sa = (uint32_t)__cvta_generic_to_shared(sdst);
    asm volatile("cp.async.cg.shared.global [%0], [%1], 16;" :: "r"(sa), "l"(gsrc));
}
__device__ __forceinline__ void cpa_commit() { asm volatile("cp.async.commit_group;"); }
__device__ __forceinline__ void cpa_wait1()  { asm volatile("cp.async.wait_group 1;"); }

__device__ __forceinline__ uint32_t packh2(float a, float b) {
    __half2 h = __floats2half2_rn(a, b);
    return *reinterpret_cast<uint32_t*>(&h);
}
__device__ __forceinline__ uint32_t h2ex2(uint32_t x) {
    uint32_t r;
    asm("ex2.approx.f16x2 %0, %1;" : "=r"(r) : "r"(x));
    return r;
}
__device__ __forceinline__ float mish_f(float x) {
    float sp = (x > 20.f) ? x : log1pf(__expf(x));
    return x * tanhf(sp);
}

// ============================================================
// merged prepass: z 0-7 fp16-convert, z 8-13 bm fuse (permuted) + passthrough
// grid (1536, 1, 14), 256 threads
// ============================================================
__global__ void prepass_kernel(
    const float* q, const float* k, const float* v,
    const float* Wq, const float* Wk, const float* Wv,
    const float* Wo1, const float* Wo2,
    const float* bias, const int* mask, float* outbias)
{
    if (blockIdx.z < 8) {
        const float* src; __half* dst; int n4;
        switch (blockIdx.z) {
            case 0: src = q;   dst = g_qr;  n4 = SN * DIN / 4;    break;
            case 1: src = k;   dst = g_kr;  n4 = SN * DIN / 4;    break;
            case 2: src = v;   dst = g_vr;  n4 = SN * DIN / 4;    break;
            case 3: src = Wq;  dst = g_Wq;  n4 = HDIM * DIN / 4;  break;
            case 4: src = Wk;  dst = g_Wk;  n4 = HDIM * DIN / 4;  break;
            case 5: src = Wv;  dst = g_Wv;  n4 = HDIM * DIN / 4;  break;
            case 6: src = Wo1; dst = g_Wo1; n4 = HDIM * HDIM / 4; break;
            default: src = Wo2; dst = g_Wo2; n4 = DIN * HDIM / 4; break;
        }
        int i4 = blockIdx.x * 256 + threadIdx.x;
        if (i4 >= n4) return;
        float4 x = *(const float4*)(src + (size_t)i4 * 4);
        uint2 r = make_uint2(packh2(x.x, x.y), packh2(x.z, x.w));
        *(uint2*)(dst + (size_t)i4 * 4) = r;
    } else {
        // bm planes: 6 planes x 1536 blocks x 256 threads x 4 elems = SN*SN
        int p = blockIdx.z - 8;
        size_t i = ((size_t)(p * 1536 + blockIdx.x) * 256 + threadIdx.x) * 4;
        float4 b = *(const float4*)(bias + i);
        int4   m = *(const int4*)(mask + i);
        *(float4*)(outbias + i) = b;
        float r[4];
        r[0] = m.x ? fmaf(b.x, LOG2E, -5.f) : -9e15f;
        r[1] = m.y ? fmaf(b.y, LOG2E, -5.f) : -9e15f;
        r[2] = m.z ? fmaf(b.z, LOG2E, -5.f) : -9e15f;
        r[3] = m.w ? fmaf(b.w, LOG2E, -5.f) : -9e15f;
        // permuted store: within 64-col block, c -> ((c&7)>>1)*16 + (c>>3)*2 + (c&1)
        size_t rowbase = (i / 64) * 64;
        int c0 = (int)(i & 63);
        #pragma unroll
        for (int j = 0; j < 4; j += 2) {
            int c = c0 + j;
            int cp = (((c & 7) >> 1) << 4) + ((c >> 3) << 1) + (c & 1);
            *(float2*)(g_bm + rowbase + cp) = make_float2(r[j], r[j + 1]);
        }
    }
}

// ============================================================
// fp16 GEMM body: BM=128, BN=64, BK=64, 256 thr, 3-stage, one barrier.
// MODE 0: scatter [H][N][64] fp16; 1: mish [N][HDIM] fp16; 2: plain fp32
// ============================================================
#define GP 72
#define GEMM_SMEM (3 * (128 * GP + 64 * GP) * 2)

template<int K, int MODE>
__device__ __forceinline__ void gemm_body(
    const __half* __restrict__ A, const __half* __restrict__ W,
    const float* __restrict__ bvec, void* __restrict__ outv, int NC, float scale,
    __half* smg)
{
    __half* AsB = smg;                 // 3 * 128*GP
    __half* WsB = smg + 3 * 128 * GP;  // 3 * 64*GP

    const int tid = threadIdx.x, lane = tid & 31, w = tid >> 5;
    const int gq = lane >> 2, tig = lane & 3;
    const int wrow = w * 16;
    const int row0 = blockIdx.y * 128, col0 = blockIdx.x * 64;
    const int NIT = K / 64;

    const uint32_t sA0 = (uint32_t)__cvta_generic_to_shared(AsB);
    const uint32_t sW0 = (uint32_t)__cvta_generic_to_shared(WsB);
    const uint32_t aLane = (((lane & 7) + ((lane >> 3) & 1) * 8) * GP + ((lane >> 4) & 1) * 8) * 2;
    const uint32_t wLane = (((lane & 7) + ((lane >> 4) & 1) * 8) * GP + ((lane >> 3) & 1) * 8) * 2;

    auto LOAD = [&](int buf, int it) {
        const int k0 = it * 64;
        __half* Ab = AsB + buf * 128 * GP;
        __half* Wb = WsB + buf * 64 * GP;
        #pragma unroll
        for (int i = 0; i < 4; i++) {
            int id = tid + i * 256, r = id >> 3, sg = (id & 7) * 8;
            cpa16(Ab + r * GP + sg, A + (size_t)(row0 + r) * K + k0 + sg);
        }
        #pragma unroll
        for (int i = 0; i < 2; i++) {
            int id = tid + i * 256, r = id >> 3, sg = (id & 7) * 8;
            cpa16(Wb + r * GP + sg, W + (size_t)(col0 + r) * K + k0 + sg);
        }
    };

    float cf[8][4] = {};
    LOAD(0, 0); cpa_commit();
    if (NIT > 1) LOAD(1, 1);
    cpa_commit();

    for (int it = 0; it < NIT; it++) {
        cpa_wait1();
        __syncthreads();
        if (it + 2 < NIT) LOAD((it + 2) % 3, it + 2);
        cpa_commit();

        const uint32_t sA = sA0 + (it % 3) * (128 * GP * 2) + aLane + wrow * GP * 2;
        const uint32_t sW = sW0 + (it % 3) * (64 * GP * 2) + wLane;
        #pragma unroll
        for (int kk = 0; kk < 4; kk++) {
            uint32_t af[4];
            ldmx4(af[0], af[1], af[2], af[3], sA + kk * 32);
            #pragma unroll
            for (int np = 0; np < 4; np++) {
                uint32_t w0, w1, w2, w3;
                ldmx4(w0, w1, w2, w3, sW + (np * 16 * GP) * 2 + kk * 32);
                mma16(cf[2 * np],     af, w0, w1);
                mma16(cf[2 * np + 1], af, w2, w3);
            }
        }
    }

    const int mr0 = row0 + wrow + gq, mr1 = mr0 + 8;
    #pragma unroll
    for (int n = 0; n < 8; n++) {
        int cg = col0 + n * 8 + tig * 2;
        float b0v = bvec[cg], b1v = bvec[cg + 1];
        float v00 = (cf[n][0] + b0v) * scale, v01 = (cf[n][1] + b1v) * scale;
        float v10 = (cf[n][2] + b0v) * scale, v11 = (cf[n][3] + b1v) * scale;
        if (MODE == 0) {
            __half* out = (__half*)outv;
            int h = cg >> 6, d = cg & 63;
            *(uint32_t*)(out + ((size_t)h * SN + mr0) * HD_ + d) = packh2(v00, v01);
            *(uint32_t*)(out + ((size_t)h * SN + mr1) * HD_ + d) = packh2(v10, v11);
        } else if (MODE == 1) {
            __half* out = (__half*)outv;
            *(uint32_t*)(out + (size_t)mr0 * HDIM + cg) = packh2(mish_f(v00), mish_f(v01));
            *(uint32_t*)(out + (size_t)mr1 * HDIM + cg) = packh2(mish_f(v10), mish_f(v11));
        } else {
            float* out = (float*)outv;
            *(float2*)(out + (size_t)mr0 * NC + cg) = make_float2(v00, v01);
            *(float2*)(out + (size_t)mr1 * NC + cg) = make_float2(v10, v11);
        }
    }
}

template<int K, int MODE>
__global__ void __launch_bounds__(256, 2) gemm_f16(
    const __half* __restrict__ A, const __half* __restrict__ W,
    const float* __restrict__ bvec, void* __restrict__ outv, int NC, float scale)
{
    extern __shared__ __half smg[];
    gemm_body<K, MODE>(A, W, bvec, outv, NC, scale, smg);
}

__global__ void __launch_bounds__(256, 2) gemm_proj3(
    const float* __restrict__ bq, const float* __restrict__ bk,
    const float* __restrict__ bv)
{
    extern __shared__ __half smg[];
    if (blockIdx.z == 0)
        gemm_body<DIN, 0>(g_qr, g_Wq, bq, g_qh, HDIM, QSC, smg);
    else if (blockIdx.z == 1)
        gemm_body<DIN, 0>(g_kr, g_Wk, bk, g_kh, HDIM, 1.0f, smg);
    else
        gemm_body<DIN, 0>(g_vr, g_Wv, bv, g_vh, HDIM, 1.0f, smg);
}

// ============================================================
// Flash attention (R13 structure): CTA = (head, 128 Q rows), 256 thr,
// 8 warps x 16 rows, triple-buffered K/V, ONE barrier per key block.
// bm is pre-permuted -> 4x float4 per row per block.
// ============================================================
#define AP 72
#define KVB (64 * AP)
#define ATTN_SMEM (3 * 2 * KVB * 2)
#define NBLK (SN / 64)

__global__ void __launch_bounds__(256, 2) attn_mma(const float* __restrict__ bm)
{
    extern __shared__ __half sma[];
    __half* KsB = sma;                  // 3 * [64][AP]
    __half* VsB = sma + 3 * KVB;        // 3 * [64][AP]

    const int h = blockIdx.x, q0 = blockIdx.y * 128;
    const int tid = threadIdx.x, lane = tid & 31, w = tid >> 5;
    const int gq = lane >> 2, tig = lane & 3;
    const int wrow = w * 16;
    const int r0 = wrow + gq, r1 = r0 + 8;

    const __half* qp    = g_qh + ((size_t)h * SN + q0) * HD_;
    const __half* kbase = g_kh + (size_t)h * SN * HD_;
    const __half* vbase = g_vh + (size_t)h * SN * HD_;

    const uint32_t sK0 = (uint32_t)__cvta_generic_to_shared(KsB);
    const uint32_t sV0 = (uint32_t)__cvta_generic_to_shared(VsB);
    const uint32_t kLane = (((lane & 7) + ((lane >> 4) & 1) * 8) * AP + ((lane >> 3) & 1) * 8) * 2;
    const uint32_t vLane = (((lane & 7) + ((lane >> 3) & 1) * 8) * AP + ((lane >> 4) & 1) * 8) * 2;

    auto LOADKV = [&](int buf, int jb) {
        const int k0 = jb * 64;
        __half* Ks = KsB + buf * KVB;
        __half* Vs = VsB + buf * KVB;
        #pragma unroll
        for (int i = 0; i < 2; i++) {
            int id = tid + i * 256, r = id >> 3, sg = (id & 7) * 8;
            cpa16(Ks + r * AP + sg, kbase + (size_t)(k0 + r) * HD_ + sg);
        }
        #pragma unroll
        for (int i = 0; i < 2; i++) {
            int id = tid + i * 256, r = id >> 3, sg = (id & 7) * 8;
            cpa16(Vs + r * AP + sg, vbase + (size_t)(k0 + r) * HD_ + sg);
        }
    };

    // Q fragments (fp16 pairs), pre-scaled 0.125*log2e
    uint32_t qf[4][4];
    #pragma unroll
    for (int kk = 0; kk < 4; kk++) {
        qf[kk][0] = *(const uint32_t*)(qp + r0 * HD_ + kk * 16 + 2 * tig);
        qf[kk][1] = *(const uint32_t*)(qp + r1 * HD_ + kk * 16 + 2 * tig);
        qf[kk][2] = *(const uint32_t*)(qp + r0 * HD_ + kk * 16 + 2 * tig + 8);
        qf[kk][3] = *(const uint32_t*)(qp + r1 * HD_ + kk * 16 + 2 * tig + 8);
    }

    LOADKV(0, 0); cpa_commit();
    LOADKV(1, 1); cpa_commit();

    float of[8][4] = {};
    float l0 = 0.f, l1 = 0.f;

    const size_t brow0 = (size_t)(q0 + r0) * SN + tig * 16;
    const size_t brow1 = (size_t)(q0 + r1) * SN + tig * 16;

    for (int jb = 0; jb < NBLK; jb++) {
        const int k0 = jb * 64;

        // bm loads: permuted layout -> 4 float4 per row
        float b0v[16], b1v[16];
        {
            const float4* p0 = (const float4*)(bm + brow0 + k0);
            const float4* p1 = (const float4*)(bm + brow1 + k0);
            #pragma unroll
            for (int i = 0; i < 4; i++) {
                *(float4*)(b0v + 4 * i) = p0[i];
                *(float4*)(b1v + 4 * i) = p1[i];
            }
        }
        float sf[8][4];
        #pragma unroll
        for (int n = 0; n < 8; n++) {
            sf[n][0] = b0v[2 * n]; sf[n][1] = b0v[2 * n + 1];
            sf[n][2] = b1v[2 * n]; sf[n][3] = b1v[2 * n + 1];
        }

        cpa_wait1();
        __syncthreads();
        if (jb + 2 < NBLK) LOADKV((jb + 2) % 3, jb + 2);
        cpa_commit();

        const uint32_t sK = sK0 + (jb % 3) * (KVB * 2) + kLane;
        const uint32_t sV = sV0 + (jb % 3) * (KVB * 2) + vLane;

        // S = log2-domain logits
        #pragma unroll
        for (int kk = 0; kk < 4; kk++) {
            #pragma unroll
            for (int np = 0; np < 4; np++) {
                uint32_t b0, b1, b2, b3;
                ldmx4(b0, b1, b2, b3, sK + (np * 16 * AP) * 2 + kk * 32);
                mma16(sf[2 * np],     qf[kk], b0, b1);
                mma16(sf[2 * np + 1], qf[kk], b2, b3);
            }
        }

        // p = 2^S, accumulate row sums, pack fp16 A-frags in place
        uint32_t* sfu = reinterpret_cast<uint32_t*>(&sf[0][0]);
        #pragma unroll
        for (int kk = 0; kk < 4; kk++) {
            uint32_t t0[2], t1[2];
            #pragma unroll
            for (int hh = 0; hh < 2; hh++) {
                int j = 2 * kk + hh;
                uint32_t p01 = h2ex2(packh2(sf[j][0], sf[j][1]));
                uint32_t p23 = h2ex2(packh2(sf[j][2], sf[j][3]));
                __half2 h01 = *reinterpret_cast<__half2*>(&p01);
                __half2 h23 = *reinterpret_cast<__half2*>(&p23);
                l0 += __half2float(h01.x) + __half2float(h01.y);
                l1 += __half2float(h23.x) + __half2float(h23.y);
                t0[hh] = p01;
                t1[hh] = p23;
            }
            sfu[4 * kk + 0] = t0[0];
            sfu[4 * kk + 1] = t1[0];
            sfu[4 * kk + 2] = t0[1];
            sfu[4 * kk + 3] = t1[1];
        }

        // O += P V  (V via ldmatrix.trans)
        #pragma unroll
        for (int kk = 0; kk < 4; kk++) {
            #pragma unroll
            for (int nt = 0; nt < 4; nt++) {
                uint32_t v0, v1, v2, v3;
                ldmx4t(v0, v1, v2, v3, sV + (kk * 16 * AP) * 2 + nt * 32);
                mma16(of[2 * nt],     sfu + 4 * kk, v0, v1);
                mma16(of[2 * nt + 1], sfu + 4 * kk, v2, v3);
            }
        }
    }

    l0 += __shfl_xor_sync(FULLM, l0, 1); l0 += __shfl_xor_sync(FULLM, l0, 2);
    l1 += __shfl_xor_sync(FULLM, l1, 1); l1 += __shfl_xor_sync(FULLM, l1, 2);

    const float inv0 = 1.f / l0, inv1 = 1.f / l1;
    #pragma unroll
    for (int n = 0; n < 8; n++) {
        int c = h * HD_ + n * 8 + tig * 2;
        *(uint32_t*)(g_vals + (size_t)(q0 + r0) * HDIM + c) = packh2(of[n][0] * inv0, of[n][1] * inv0);
        *(uint32_t*)(g_vals + (size_t)(q0 + r1) * HDIM + c) = packh2(of[n][2] * inv1, of[n][3] * inv1);
    }
}

// ============================================================
extern "C" void kernel_launch(void* const* d_in, const int* in_sizes, int n_in,
                              void* d_out, int out_size) {
    const float* q    = (const float*)d_in[0];
    const float* k    = (const float*)d_in[1];
    const float* v    = (const float*)d_in[2];
    const float* bias = (const float*)d_in[3];
    const int*   mask = (const int*)d_in[4];
    const float* Wq   = (const float*)d_in[5];
    const float* bq   = (const float*)d_in[6];
    const float* Wk   = (const float*)d_in[7];
    const float* bk   = (const float*)d_in[8];
    const float* Wv   = (const float*)d_in[9];
    const float* bv   = (const float*)d_in[10];
    const float* Wo1  = (const float*)d_in[11];
    const float* bo1  = (const float*)d_in[12];
    const float* Wo2  = (const float*)d_in[13];
    const float* bo2  = (const float*)d_in[14];
    float* out = (float*)d_out;

    __half *p_vals, *p_hid, *p_Wo1, *p_Wo2;
    float *p_bm;
    cudaGetSymbolAddress((void**)&p_vals, g_vals);
    cudaGetSymbolAddress((void**)&p_hid, g_hid);
    cudaGetSymbolAddress((void**)&p_bm,  g_bm);
    cudaGetSymbolAddress((void**)&p_Wo1, g_Wo1);
    cudaGetSymbolAddress((void**)&p_Wo2, g_Wo2);

    cudaFuncSetAttribute(gemm_proj3,        cudaFuncAttributeMaxDynamicSharedMemorySize, GEMM_SMEM);
    cudaFuncSetAttribute(gemm_f16<HDIM, 1>, cudaFuncAttributeMaxDynamicSharedMemorySize, GEMM_SMEM);
    cudaFuncSetAttribute(gemm_f16<HDIM, 2>, cudaFuncAttributeMaxDynamicSharedMemorySize, GEMM_SMEM);
    cudaFuncSetAttribute(attn_mma, cudaFuncAttributeMaxDynamicSharedMemorySize, ATTN_SMEM);

    dim3 blk(256);

    // 0) merged prepass: converts + bm fuse (permuted) + bias passthrough
    prepass_kernel<<<dim3(1536, 1, 14), blk>>>(q, k, v, Wq, Wk, Wv, Wo1, Wo2,
                                               bias, mask, out + (size_t)SN * DIN);

    // 1) projections (Q pre-scaled by 0.125*log2e)
    dim3 gp(HDIM / 64, SN / 128, 3);
    gemm_proj3<<<gp, blk, GEMM_SMEM>>>(bq, bk, bv);

    // 2) flash attention
    dim3 ga(NH, SN / 128);
    attn_mma<<<ga, blk, ATTN_SMEM>>>(p_bm);

    // 3) MLP
    dim3 g1(HDIM / 64, SN / 128);
    gemm_f16<HDIM, 1><<<g1, blk, GEMM_SMEM>>>(p_vals, p_Wo1, bo1, p_hid, HDIM, 1.0f);
    dim3 g2(DIN / 64, SN / 128);
    gemm_f16<HDIM, 2><<<g2, blk, GEMM_SMEM>>>(p_hid, p_Wo2, bo2, out, DIN, 1.0f);
}